// round 2
// baseline (speedup 1.0000x reference)
#include <cuda_runtime.h>
#include <math.h>

#define HID   256
#define BSZ   64
#define DCS   16
#define NCLS  60
#define NKEY  (NCLS*DCS)     // 960
#define NTOK  (BSZ*DCS)      // 1024
#define QSZ   5
#define TOPK  5
#define TOPKQ 100
#define NQ    400            // 5*5*16 candidates per token
#define CLSBLK (QSZ*DCS)     // 80 rows per class block (within candidate set)

// ---------------- scratch (device globals; no allocation allowed) ----------------
__device__ float g_key_t[NKEY*HID];      // transformed memory keys
__device__ float g_query[NTOK*HID];      // h @ query_w^T + b
__device__ float g_qq   [NTOK*HID];      // h @ qq_w^T + b
__device__ float g_qk   [NTOK*HID];      // qq @ kq_w   (folded level-2 query)
__device__ float g_W1   [NTOK*NKEY];     // level-1 scores
__device__ float g_qraw [NTOK*HID];      // softmax-weighted raw queue rows
__device__ float g_cat  [NTOK*2*HID];    // [queue | memory_z]
__device__ int   g_cls  [NTOK*TOPK];     // selected classes per token

// ---------------- generic tiled SGEMM: C = A @ op(B) + bias ----------------
// A: M x K row-major (lda). TRANSB: B is N x K (torch weight). else B is K x N.
// grid = (N/64, M/64), 256 threads, 4x4 micro-tile. All dims multiples of 64/16.
template<bool TRANSB>
__global__ void sgemm_kernel(const float* __restrict__ A, int lda,
                             const float* __restrict__ B, int ldb,
                             const float* __restrict__ bias,
                             float* __restrict__ C, int ldc, int K)
{
    __shared__ float As[16][65];
    __shared__ float Bs[16][65];
    const int tid = threadIdx.x;
    const int tx = tid & 15, ty = tid >> 4;
    const int row0 = blockIdx.y * 64, col0 = blockIdx.x * 64;

    float acc[4][4] = {};
    const int ar = tid >> 2, ac = (tid & 3) << 2;   // 4 consecutive k per thread

    for (int k0 = 0; k0 < K; k0 += 16) {
        float4 av = *(const float4*)(A + (size_t)(row0 + ar) * lda + k0 + ac);
        As[ac+0][ar] = av.x; As[ac+1][ar] = av.y; As[ac+2][ar] = av.z; As[ac+3][ar] = av.w;
        if (TRANSB) {
            float4 bv = *(const float4*)(B + (size_t)(col0 + ar) * ldb + k0 + ac);
            Bs[ac+0][ar] = bv.x; Bs[ac+1][ar] = bv.y; Bs[ac+2][ar] = bv.z; Bs[ac+3][ar] = bv.w;
        } else {
            const int bk = tid >> 4, bn = (tid & 15) << 2;
            float4 bv = *(const float4*)(B + (size_t)(k0 + bk) * ldb + col0 + bn);
            Bs[bk][bn+0] = bv.x; Bs[bk][bn+1] = bv.y; Bs[bk][bn+2] = bv.z; Bs[bk][bn+3] = bv.w;
        }
        __syncthreads();
        #pragma unroll
        for (int kk = 0; kk < 16; kk++) {
            float a[4], b[4];
            #pragma unroll
            for (int i = 0; i < 4; i++) a[i] = As[kk][ty*4+i];
            #pragma unroll
            for (int j = 0; j < 4; j++) b[j] = Bs[kk][tx*4+j];
            #pragma unroll
            for (int i = 0; i < 4; i++)
                #pragma unroll
                for (int j = 0; j < 4; j++)
                    acc[i][j] += a[i] * b[j];
        }
        __syncthreads();
    }
    #pragma unroll
    for (int j = 0; j < 4; j++) {
        const float bj = bias ? bias[col0 + tx*4 + j] : 0.f;
        #pragma unroll
        for (int i = 0; i < 4; i++)
            C[(size_t)(row0 + ty*4 + i) * ldc + col0 + tx*4 + j] = acc[i][j] + bj;
    }
}

// ---------------- level 1: top-5 per token, softmax, weighted key sum ----------------
// one warp per token; 4 warps per block
__global__ void top5_kernel()
{
    const int lane = threadIdx.x & 31;
    const int n = blockIdx.x * 4 + (threadIdx.x >> 5);
    const float* __restrict__ row = g_W1 + (size_t)n * NKEY;

    // lane-local sorted-desc top5 over strided stripe (30 values/lane)
    float v[5]; int ix[5];
    #pragma unroll
    for (int j = 0; j < 5; j++) { v[j] = -INFINITY; ix[j] = 0; }
    for (int k = lane; k < NKEY; k += 32) {
        float x = row[k];
        if (x > v[4]) {
            v[4] = x; ix[4] = k;
            #pragma unroll
            for (int p = 4; p > 0; p--) {
                if (v[p] > v[p-1]) {
                    float tv = v[p]; v[p] = v[p-1]; v[p-1] = tv;
                    int   ti = ix[p]; ix[p] = ix[p-1]; ix[p-1] = ti;
                }
            }
        }
    }

    // merge across lanes: 5 iterations of warp argmax; winner pops its list head
    float selv[5]; int seli[5];
    #pragma unroll
    for (int j = 0; j < 5; j++) {
        float cand = v[0]; int candi = ix[0];
        float bv = cand; int bl = lane;
        #pragma unroll
        for (int off = 16; off; off >>= 1) {
            float ov = __shfl_down_sync(0xffffffffu, bv, off);
            int   ol = __shfl_down_sync(0xffffffffu, bl, off);
            if (ov > bv) { bv = ov; bl = ol; }
        }
        bl = __shfl_sync(0xffffffffu, bl, 0);
        selv[j] = __shfl_sync(0xffffffffu, cand, bl);
        seli[j] = __shfl_sync(0xffffffffu, candi, bl);
        if (lane == bl) {
            #pragma unroll
            for (int p = 0; p < 4; p++) { v[p] = v[p+1]; ix[p] = ix[p+1]; }
            v[4] = -INFINITY;
        }
    }

    // softmax over 5 (all lanes hold identical values)
    const float mx = selv[0];
    float e[5]; float s = 0.f;
    #pragma unroll
    for (int j = 0; j < 5; j++) { e[j] = expf(selv[j] - mx); s += e[j]; }
    const float inv = 1.f / s;

    // memory_z[n] = sum_j w_j * key_t[seli_j]  ->  g_cat[n][256:512]
    #pragma unroll
    for (int c = 0; c < 8; c++) {
        const int col = c * 32 + lane;
        float acc = 0.f;
        #pragma unroll
        for (int j = 0; j < 5; j++) acc += e[j] * g_key_t[(size_t)seli[j] * HID + col];
        g_cat[(size_t)n * 512 + 256 + col] = acc * inv;
    }
    // class indices (predicated writes; avoids local-mem dynamic index)
    #pragma unroll
    for (int j = 0; j < 5; j++)
        if (lane == j) g_cls[n * 5 + j] = seli[j] / DCS;
}

// ---------------- level 2: score 400, top-100, softmax, weighted raw gather ----------------
// one block (256 threads) per token
__global__ void queue_kernel(const float* __restrict__ qkey)
{
    __shared__ float qk_s[HID];
    __shared__ float sval[512];
    __shared__ int   sidx[512];
    __shared__ int   cls_s[5];
    __shared__ float inv_total;

    const int n = blockIdx.x;
    const int tid = threadIdx.x;
    const int lane = tid & 31, warp = tid >> 5;

    qk_s[tid] = g_qk[(size_t)n * HID + tid];
    if (tid < 5) cls_s[tid] = g_cls[n * 5 + tid];
    __syncthreads();

    // 400 scores: warp per score, 50 rounds of 8 warps
    for (int it = 0; it < 50; it++) {
        const int m = it * 8 + warp;         // candidate index
        const int k = m / CLSBLK;            // which of the 5 classes
        const int r = m - k * CLSBLK;        // row within class block (q*16+s)
        const int ri = cls_s[k] * CLSBLK + r;  // global queue row 0..4799
        const float* __restrict__ kr = qkey + (size_t)ri * HID;
        float s = 0.f;
        #pragma unroll
        for (int j = 0; j < 8; j++) {
            const int e = j * 32 + lane;
            s += kr[e] * qk_s[e];
        }
        #pragma unroll
        for (int off = 16; off; off >>= 1) s += __shfl_down_sync(0xffffffffu, s, off);
        if (lane == 0) { sval[m] = s; sidx[m] = ri; }
    }
    for (int s2 = tid; s2 < 512; s2 += 256)
        if (s2 >= NQ) { sval[s2] = -INFINITY; sidx[s2] = 0; }
    __syncthreads();

    // bitonic sort 512, descending, keyed by value with index payload
    for (int k = 2; k <= 512; k <<= 1) {
        for (int j = k >> 1; j > 0; j >>= 1) {
            for (int i = tid; i < 512; i += 256) {
                const int ixj = i ^ j;
                if (ixj > i) {
                    const bool up = ((i & k) == 0);
                    const float a = sval[i], b = sval[ixj];
                    if (up ? (a < b) : (a > b)) {
                        sval[i] = b; sval[ixj] = a;
                        const int t = sidx[i]; sidx[i] = sidx[ixj]; sidx[ixj] = t;
                    }
                }
            }
            __syncthreads();
        }
    }

    // softmax over top 100
    const float mx = sval[0];
    __syncthreads();                 // FIX: all threads must read max before tid 0 overwrites sval[0]
    if (tid < TOPKQ) sval[tid] = expf(sval[tid] - mx);
    __syncthreads();
    if (tid == 0) {
        float t = 0.f;
        for (int j = 0; j < TOPKQ; j++) t += sval[j];
        inv_total = 1.f / t;
    }
    __syncthreads();
    if (tid < TOPKQ) sval[tid] *= inv_total;
    __syncthreads();

    // weighted sum of raw rows; thread = output column (coalesced row reads)
    float acc = 0.f;
    for (int j = 0; j < TOPKQ; j++)
        acc += sval[j] * qkey[(size_t)sidx[j] * HID + tid];
    g_qraw[(size_t)n * HID + tid] = acc;
}

// ---------------- host ----------------
extern "C" void kernel_launch(void* const* d_in, const int* in_sizes, int n_in,
                              void* d_out, int out_size)
{
    const float* h          = (const float*)d_in[0];
    // d_in[1] labels, d_in[2] tag: unused
    const float* memory_key = (const float*)d_in[3];
    const float* queue_key  = (const float*)d_in[4];
    const float* key_w      = (const float*)d_in[5];
    const float* key_b      = (const float*)d_in[6];
    const float* query_w    = (const float*)d_in[7];
    const float* query_b    = (const float*)d_in[8];
    const float* kq_w       = (const float*)d_in[9];
    const float* kq_b       = (const float*)d_in[10];
    const float* qq_w       = (const float*)d_in[11];
    const float* qq_b       = (const float*)d_in[12];
    const float* proto_w    = (const float*)d_in[13];
    const float* proto_b    = (const float*)d_in[14];
    float* out = (float*)d_out;

    float *p_key_t, *p_query, *p_qq, *p_qk, *p_W1, *p_qraw, *p_cat;
    cudaGetSymbolAddress((void**)&p_key_t, g_key_t);
    cudaGetSymbolAddress((void**)&p_query, g_query);
    cudaGetSymbolAddress((void**)&p_qq,    g_qq);
    cudaGetSymbolAddress((void**)&p_qk,    g_qk);
    cudaGetSymbolAddress((void**)&p_W1,    g_W1);
    cudaGetSymbolAddress((void**)&p_qraw,  g_qraw);
    cudaGetSymbolAddress((void**)&p_cat,   g_cat);

    // key_t = memory_key @ key_w^T + key_b           (960 x 256, K=256)
    sgemm_kernel<true><<<dim3(HID/64, NKEY/64), 256>>>(memory_key, HID, key_w, HID, key_b, p_key_t, HID, HID);
    // query = h @ query_w^T + query_b                (1024 x 256)
    sgemm_kernel<true><<<dim3(HID/64, NTOK/64), 256>>>(h, HID, query_w, HID, query_b, p_query, HID, HID);
    // qq = h @ qq_w^T + qq_b                         (1024 x 256)
    sgemm_kernel<true><<<dim3(HID/64, NTOK/64), 256>>>(h, HID, qq_w, HID, qq_b, p_qq, HID, HID);
    // qk = qq @ kq_w  (fold; bias dropped — shift-invariant under topk+softmax)
    sgemm_kernel<false><<<dim3(HID/64, NTOK/64), 256>>>(p_qq, HID, kq_w, HID, nullptr, p_qk, HID, HID);
    // W1 = query @ key_t^T                           (1024 x 960)
    sgemm_kernel<true><<<dim3(NKEY/64, NTOK/64), 256>>>(p_query, HID, p_key_t, HID, nullptr, p_W1, NKEY, HID);
    // level-1 topk/softmax/weighted-sum -> cat[:,256:512], class indices
    top5_kernel<<<NTOK/4, 128>>>();
    // level-2 scoring/topk/softmax/raw gather -> qraw
    queue_kernel<<<NTOK, 256>>>(queue_key);
    // queue = qraw @ kq_w^T + kq_b -> cat[:,0:256]   (Σw=1 makes this exact)
    sgemm_kernel<true><<<dim3(HID/64, NTOK/64), 256>>>(p_qraw, HID, kq_w, HID, kq_b, p_cat, 2*HID, HID);
    // out = cat @ proto_w^T + proto_b                (1024 x 256, K=512)
    sgemm_kernel<true><<<dim3(HID/64, NTOK/64), 256>>>(p_cat, 2*HID, proto_w, 2*HID, proto_b, out, HID, 2*HID);
}

// round 4
// speedup vs baseline: 1.4101x; 1.4101x over previous
#include <cuda_runtime.h>
#include <math.h>

#define HID   256
#define BSZ   64
#define DCS   16
#define NCLS  60
#define NKEY  (NCLS*DCS)     // 960
#define NTOK  (BSZ*DCS)      // 1024
#define QSZ   5
#define TOPK  5
#define TOPKQ 100
#define NQ    400            // 5*5*16 candidates per token
#define CLSBLK (QSZ*DCS)     // 80 rows per class block

// ---------------- scratch (device globals) ----------------
__device__ float g_key_t[NKEY*HID];      // transformed memory keys
__device__ float g_query[NTOK*HID];      // h @ query_w^T + b
__device__ float g_qk   [NTOK*HID];      // folded level-2 query  h @ Wc + bc
__device__ float g_W1   [NTOK*NKEY];     // level-1 scores
__device__ float g_cat  [NTOK*2*HID];    // [qraw | memory_z]
__device__ int   g_cls  [NTOK*TOPK];     // selected classes per token
__device__ float g_Wc   [HID*HID];       // qq_w^T @ kq_w
__device__ float g_bc   [HID];           // qq_b @ kq_w
__device__ float g_Wout [HID*2*HID];     // [proto_w_q @ kq_w | proto_w_m]  (256 x 512)
__device__ float g_bout [HID];           // kq_b @ proto_w_q^T + proto_b

// ---------------- 32x64 tile GEMM core, 128 threads ----------------
// AMODE: 0 = A row-major (M x K), 1 = A is K x M (read transposed)
// BMODE: 0 = B is K x N,          1 = B is N x K (torch weight)
template<int AMODE, int BMODE>
__device__ __forceinline__ void gemm_tile(
    float* As, float* Bs,                       // As: 16*36 floats, Bs: 16*64 floats
    const float* __restrict__ A, int lda,
    const float* __restrict__ B, int ldb,
    const float* __restrict__ bias,
    float* __restrict__ C, int ldc, int K, int row0, int col0)
{
    const int tid = threadIdx.x;
    const int tx = tid & 15, ty = tid >> 4;
    float acc[4][4] = {};

    for (int k0 = 0; k0 < K; k0 += 16) {
        // ---- load A tile (32 x 16) ----
        if (AMODE == 0) {
            const int ar = tid >> 2, ac = (tid & 3) << 2;
            float4 av = *(const float4*)(A + (size_t)(row0 + ar) * lda + k0 + ac);
            As[(ac+0)*36 + ar] = av.x; As[(ac+1)*36 + ar] = av.y;
            As[(ac+2)*36 + ar] = av.z; As[(ac+3)*36 + ar] = av.w;
        } else {
            const int kr = tid >> 3, cm = (tid & 7) << 2;
            float4 av = *(const float4*)(A + (size_t)(k0 + kr) * lda + row0 + cm);
            *(float4*)(As + kr*36 + cm) = av;
        }
        // ---- load B tile (16 x 64) ----
        if (BMODE == 1) {
            #pragma unroll
            for (int i = 0; i < 2; i++) {
                const int br = i*32 + (tid >> 2), kc = (tid & 3) << 2;
                float4 bv = *(const float4*)(B + (size_t)(col0 + br) * ldb + k0 + kc);
                Bs[(kc+0)*64 + br] = bv.x; Bs[(kc+1)*64 + br] = bv.y;
                Bs[(kc+2)*64 + br] = bv.z; Bs[(kc+3)*64 + br] = bv.w;
            }
        } else {
            #pragma unroll
            for (int i = 0; i < 2; i++) {
                const int kr = i*8 + (tid >> 4), cn = (tid & 15) << 2;
                *(float4*)(Bs + kr*64 + cn) =
                    *(const float4*)(B + (size_t)(k0 + kr) * ldb + col0 + cn);
            }
        }
        __syncthreads();
        #pragma unroll
        for (int kk = 0; kk < 16; kk++) {
            float4 a = *(const float4*)(As + kk*36 + ty*4);
            float4 b = *(const float4*)(Bs + kk*64 + tx*4);
            acc[0][0] += a.x*b.x; acc[0][1] += a.x*b.y; acc[0][2] += a.x*b.z; acc[0][3] += a.x*b.w;
            acc[1][0] += a.y*b.x; acc[1][1] += a.y*b.y; acc[1][2] += a.y*b.z; acc[1][3] += a.y*b.w;
            acc[2][0] += a.z*b.x; acc[2][1] += a.z*b.y; acc[2][2] += a.z*b.z; acc[2][3] += a.z*b.w;
            acc[3][0] += a.w*b.x; acc[3][1] += a.w*b.y; acc[3][2] += a.w*b.z; acc[3][3] += a.w*b.w;
        }
        __syncthreads();
    }

    float4 bv = make_float4(0.f, 0.f, 0.f, 0.f);
    if (bias) bv = *(const float4*)(bias + col0 + tx*4);
    #pragma unroll
    for (int i = 0; i < 4; i++) {
        float4 o = make_float4(acc[i][0] + bv.x, acc[i][1] + bv.y,
                               acc[i][2] + bv.z, acc[i][3] + bv.w);
        *(float4*)(C + (size_t)(row0 + ty*4 + i) * ldc + col0 + tx*4) = o;
    }
}

// ---------------- launch A: all input-independent-chain work, batched ----------------
// blocks: [0,120) key_t | [120,248) query | [248,280) Wc | [280,312) Wpq
//         [312,328) copy proto_w_m -> Wout | [328,330) bias vectors
__global__ void frontA_kernel(const float* __restrict__ memory_key,
                              const float* __restrict__ key_w, const float* __restrict__ key_b,
                              const float* __restrict__ h,
                              const float* __restrict__ query_w, const float* __restrict__ query_b,
                              const float* __restrict__ qq_w, const float* __restrict__ qq_b,
                              const float* __restrict__ kq_w, const float* __restrict__ kq_b,
                              const float* __restrict__ proto_w, const float* __restrict__ proto_b)
{
    __shared__ float As[16*36];
    __shared__ float Bs[16*64];
    const int b = blockIdx.x;
    const int tid = threadIdx.x;

    if (b < 120) {
        gemm_tile<0,1>(As, Bs, memory_key, HID, key_w, HID, key_b,
                       g_key_t, HID, HID, (b >> 2) * 32, (b & 3) * 64);
    } else if (b < 248) {
        const int b2 = b - 120;
        gemm_tile<0,1>(As, Bs, h, HID, query_w, HID, query_b,
                       g_query, HID, HID, (b2 >> 2) * 32, (b2 & 3) * 64);
    } else if (b < 280) {
        const int b2 = b - 248;   // Wc[d,j] = sum_i qq_w[i,d] kq_w[i,j]
        gemm_tile<1,0>(As, Bs, qq_w, HID, kq_w, HID, nullptr,
                       g_Wc, HID, HID, (b2 >> 2) * 32, (b2 & 3) * 64);
    } else if (b < 312) {
        const int b2 = b - 280;   // Wpq[j,c] = sum_h proto_w[j,h] kq_w[h,c] -> Wout[:, 0:256]
        gemm_tile<0,0>(As, Bs, proto_w, 2*HID, kq_w, HID, nullptr,
                       g_Wout, 2*HID, HID, (b2 >> 2) * 32, (b2 & 3) * 64);
    } else if (b < 328) {
        const int b2 = b - 312;   // copy proto_w[:,256:512] -> Wout[:,256:512]
        #pragma unroll
        for (int t = 0; t < 8; t++) {
            const int idx = t * 128 + tid;               // 0..1023
            const int row = b2 * 16 + (idx >> 6);
            const int c4  = idx & 63;
            *(float4*)(g_Wout + (size_t)row * 512 + 256 + c4 * 4) =
                *(const float4*)(proto_w + (size_t)row * 512 + 256 + c4 * 4);
        }
    } else {
        const int j = (b - 328) * 128 + tid;             // 0..255
        float s = 0.f;                                    // bc[j] = sum_i qq_b[i] kq_w[i,j]
        for (int i = 0; i < HID; i++) s += qq_b[i] * kq_w[i * HID + j];
        g_bc[j] = s;
        float s2 = proto_b[j];                            // bout[j] = sum_h kq_b[h] proto_w[j,h] + proto_b[j]
        for (int i = 0; i < HID; i++) s2 += kq_b[i] * proto_w[(size_t)j * 512 + i];
        g_bout[j] = s2;
    }
}

// ---------------- launch B: qk + W1, batched ----------------
__global__ void midB_kernel(const float* __restrict__ h)
{
    __shared__ float As[16*36];
    __shared__ float Bs[16*64];
    const int b = blockIdx.x;
    if (b < 128) {
        gemm_tile<0,0>(As, Bs, h, HID, g_Wc, HID, g_bc,
                       g_qk, HID, HID, (b >> 2) * 32, (b & 3) * 64);
    } else {
        const int b2 = b - 128;   // W1 = query @ key_t^T, N=960 -> 15 tiles
        gemm_tile<0,1>(As, Bs, g_query, HID, g_key_t, HID, nullptr,
                       g_W1, NKEY, HID, (b2 / 15) * 32, (b2 % 15) * 64);
    }
}

// ---------------- launch E: out = cat @ Wout^T + bout ----------------
__global__ void outE_kernel(float* __restrict__ out)
{
    __shared__ float As[16*36];
    __shared__ float Bs[16*64];
    const int b = blockIdx.x;
    gemm_tile<0,1>(As, Bs, g_cat, 2*HID, g_Wout, 2*HID, g_bout,
                   out, HID, 2*HID, (b >> 2) * 32, (b & 3) * 64);
}

// ---------------- level 1: top-5 per token ----------------
__global__ void top5_kernel()
{
    const int lane = threadIdx.x & 31;
    const int n = blockIdx.x * 4 + (threadIdx.x >> 5);
    const float* __restrict__ row = g_W1 + (size_t)n * NKEY;

    float v[5]; int ix[5];
    #pragma unroll
    for (int j = 0; j < 5; j++) { v[j] = -INFINITY; ix[j] = 0; }
    for (int k = lane; k < NKEY; k += 32) {
        float x = row[k];
        if (x > v[4]) {
            v[4] = x; ix[4] = k;
            #pragma unroll
            for (int p = 4; p > 0; p--) {
                if (v[p] > v[p-1]) {
                    float tv = v[p]; v[p] = v[p-1]; v[p-1] = tv;
                    int   ti = ix[p]; ix[p] = ix[p-1]; ix[p-1] = ti;
                }
            }
        }
    }

    float selv[5]; int seli[5];
    #pragma unroll
    for (int j = 0; j < 5; j++) {
        float cand = v[0]; int candi = ix[0];
        float bv = cand; int bl = lane;
        #pragma unroll
        for (int off = 16; off; off >>= 1) {
            float ov = __shfl_down_sync(0xffffffffu, bv, off);
            int   ol = __shfl_down_sync(0xffffffffu, bl, off);
            if (ov > bv) { bv = ov; bl = ol; }
        }
        bl = __shfl_sync(0xffffffffu, bl, 0);
        selv[j] = __shfl_sync(0xffffffffu, cand, bl);
        seli[j] = __shfl_sync(0xffffffffu, candi, bl);
        if (lane == bl) {
            #pragma unroll
            for (int p = 0; p < 4; p++) { v[p] = v[p+1]; ix[p] = ix[p+1]; }
            v[4] = -INFINITY;
        }
    }

    const float mx = selv[0];
    float e[5]; float s = 0.f;
    #pragma unroll
    for (int j = 0; j < 5; j++) { e[j] = expf(selv[j] - mx); s += e[j]; }
    const float inv = 1.f / s;

    #pragma unroll
    for (int c = 0; c < 8; c++) {
        const int col = c * 32 + lane;
        float acc = 0.f;
        #pragma unroll
        for (int j = 0; j < 5; j++) acc += e[j] * g_key_t[(size_t)seli[j] * HID + col];
        g_cat[(size_t)n * 512 + 256 + col] = acc * inv;
    }
    #pragma unroll
    for (int j = 0; j < 5; j++)
        if (lane == j) g_cls[n * 5 + j] = seli[j] / DCS;
}

// ---------------- level 2: score 400, top-100, softmax, weighted raw gather ----------------
__global__ void queue_kernel(const float* __restrict__ qkey)
{
    __shared__ float qk_s[HID];
    __shared__ float sval[512];
    __shared__ int   sidx[512];
    __shared__ int   cls_s[5];
    __shared__ float inv_total;
    __shared__ float4 sacc[256];

    const int n = blockIdx.x;
    const int tid = threadIdx.x;
    const int lane = tid & 31, warp = tid >> 5;

    qk_s[tid] = g_qk[(size_t)n * HID + tid];
    if (tid < 5) cls_s[tid] = g_cls[n * 5 + tid];
    __syncthreads();

    // 400 scores: warp per score, float4 loads (2 x LDG.128 per row per lane)
    const float4* __restrict__ qs4 = (const float4*)qk_s;
    const float4 a1 = qs4[lane], a2 = qs4[32 + lane];
    for (int it = 0; it < 50; it++) {
        const int m = it * 8 + warp;
        const int k = m / CLSBLK;
        const int r = m - k * CLSBLK;
        const int ri = cls_s[k] * CLSBLK + r;
        const float4* __restrict__ kr4 = (const float4*)(qkey + (size_t)ri * HID);
        const float4 k1 = kr4[lane], k2 = kr4[32 + lane];
        float s = k1.x*a1.x + k1.y*a1.y + k1.z*a1.z + k1.w*a1.w
                + k2.x*a2.x + k2.y*a2.y + k2.z*a2.z + k2.w*a2.w;
        #pragma unroll
        for (int off = 16; off; off >>= 1) s += __shfl_down_sync(0xffffffffu, s, off);
        if (lane == 0) { sval[m] = s; sidx[m] = ri; }
    }
    for (int s2 = tid; s2 < 512; s2 += 256)
        if (s2 >= NQ) { sval[s2] = -INFINITY; sidx[s2] = 0; }
    __syncthreads();

    // bitonic sort 512 desc
    for (int k = 2; k <= 512; k <<= 1) {
        for (int j = k >> 1; j > 0; j >>= 1) {
            for (int i = tid; i < 512; i += 256) {
                const int ixj = i ^ j;
                if (ixj > i) {
                    const bool up = ((i & k) == 0);
                    const float a = sval[i], bq = sval[ixj];
                    if (up ? (a < bq) : (a > bq)) {
                        sval[i] = bq; sval[ixj] = a;
                        const int t = sidx[i]; sidx[i] = sidx[ixj]; sidx[ixj] = t;
                    }
                }
            }
            __syncthreads();
        }
    }

    // softmax over top 100
    const float mx = sval[0];
    __syncthreads();
    if (tid < TOPKQ) sval[tid] = expf(sval[tid] - mx);
    __syncthreads();
    if (tid < 32) {
        float t = 0.f;
        for (int j = tid; j < TOPKQ; j += 32) t += sval[j];
        #pragma unroll
        for (int off = 16; off; off >>= 1) t += __shfl_down_sync(0xffffffffu, t, off);
        if (tid == 0) inv_total = 1.f / t;
    }
    __syncthreads();
    if (tid < TOPKQ) sval[tid] *= inv_total;
    __syncthreads();

    // weighted sum of raw rows: 4 row-groups x 64 float4-columns
    const int rg = tid >> 6, c4 = tid & 63;
    const float4* __restrict__ q4 = (const float4*)qkey;
    float4 acc = make_float4(0.f, 0.f, 0.f, 0.f);
    for (int j = rg; j < TOPKQ; j += 4) {
        const float w = sval[j];
        const float4 v = q4[(size_t)sidx[j] * 64 + c4];
        acc.x += w * v.x; acc.y += w * v.y; acc.z += w * v.z; acc.w += w * v.w;
    }
    sacc[rg * 64 + c4] = acc;
    __syncthreads();
    if (rg == 0) {
        const float4 p0 = sacc[c4], p1 = sacc[64 + c4], p2 = sacc[128 + c4], p3 = sacc[192 + c4];
        float4 o = make_float4(p0.x + p1.x + p2.x + p3.x, p0.y + p1.y + p2.y + p3.y,
                               p0.z + p1.z + p2.z + p3.z, p0.w + p1.w + p2.w + p3.w);
        *(float4*)(g_cat + (size_t)n * 512 + c4 * 4) = o;
    }
}

// ---------------- host ----------------
extern "C" void kernel_launch(void* const* d_in, const int* in_sizes, int n_in,
                              void* d_out, int out_size)
{
    const float* h          = (const float*)d_in[0];
    const float* memory_key = (const float*)d_in[3];
    const float* queue_key  = (const float*)d_in[4];
    const float* key_w      = (const float*)d_in[5];
    const float* key_b      = (const float*)d_in[6];
    const float* query_w    = (const float*)d_in[7];
    const float* query_b    = (const float*)d_in[8];
    const float* kq_w       = (const float*)d_in[9];
    const float* kq_b       = (const float*)d_in[10];
    const float* qq_w       = (const float*)d_in[11];
    const float* qq_b       = (const float*)d_in[12];
    const float* proto_w    = (const float*)d_in[13];
    const float* proto_b    = (const float*)d_in[14];
    float* out = (float*)d_out;

    // A: key_t, query, Wc, Wout(+copy), biases — all independent
    frontA_kernel<<<330, 128>>>(memory_key, key_w, key_b, h, query_w, query_b,
                                qq_w, qq_b, kq_w, kq_b, proto_w, proto_b);
    // B: qk = h@Wc + bc ; W1 = query@key_t^T
    midB_kernel<<<608, 128>>>(h);
    // C: level-1 top5 -> memory_z, classes
    top5_kernel<<<NTOK/4, 128>>>();
    // D: level-2 score/top100/softmax/gather -> g_cat[:,0:256]
    queue_kernel<<<NTOK, 256>>>(queue_key);
    // E: out = cat @ Wout^T + bout
    outE_kernel<<<128, 128>>>(out);
}

// round 5
// speedup vs baseline: 1.6215x; 1.1499x over previous
#include <cuda_runtime.h>
#include <math.h>

#define HID   256
#define BSZ   64
#define DCS   16
#define NCLS  60
#define NKEY  (NCLS*DCS)     // 960
#define NTOK  (BSZ*DCS)      // 1024
#define QSZ   5
#define TOPK  5
#define TOPKQ 100
#define NQ    400            // 5*5*16 candidates per token
#define CLSBLK (QSZ*DCS)     // 80 rows per class block

// ---------------- scratch (device globals) ----------------
__device__ float g_key_t[NKEY*HID];      // transformed memory keys
__device__ float g_query[NTOK*HID];      // h @ query_w^T + b
__device__ float g_qk   [NTOK*HID];      // folded level-2 query  h @ Wc + bc
__device__ float g_W1   [NTOK*NKEY];     // level-1 scores
__device__ float g_cat  [NTOK*2*HID];    // [qraw | memory_z]
__device__ int   g_cls  [NTOK*TOPK];     // selected classes per token
__device__ float g_Wc   [HID*HID];       // qq_w^T @ kq_w
__device__ float g_bc   [HID];           // qq_b @ kq_w
__device__ float g_Wout [HID*2*HID];     // [proto_w_q @ kq_w | proto_w_m]  (256 x 512)
__device__ float g_bout [HID];           // kq_b @ proto_w_q^T + proto_b

// ---------------- 32x64 tile GEMM core, 128 threads ----------------
template<int AMODE, int BMODE>
__device__ __forceinline__ void gemm_tile(
    float* As, float* Bs,
    const float* __restrict__ A, int lda,
    const float* __restrict__ B, int ldb,
    const float* __restrict__ bias,
    float* __restrict__ C, int ldc, int K, int row0, int col0)
{
    const int tid = threadIdx.x;
    const int tx = tid & 15, ty = tid >> 4;
    float acc[4][4] = {};

    for (int k0 = 0; k0 < K; k0 += 16) {
        if (AMODE == 0) {
            const int ar = tid >> 2, ac = (tid & 3) << 2;
            float4 av = *(const float4*)(A + (size_t)(row0 + ar) * lda + k0 + ac);
            As[(ac+0)*36 + ar] = av.x; As[(ac+1)*36 + ar] = av.y;
            As[(ac+2)*36 + ar] = av.z; As[(ac+3)*36 + ar] = av.w;
        } else {
            const int kr = tid >> 3, cm = (tid & 7) << 2;
            float4 av = *(const float4*)(A + (size_t)(k0 + kr) * lda + row0 + cm);
            *(float4*)(As + kr*36 + cm) = av;
        }
        if (BMODE == 1) {
            #pragma unroll
            for (int i = 0; i < 2; i++) {
                const int br = i*32 + (tid >> 2), kc = (tid & 3) << 2;
                float4 bv = *(const float4*)(B + (size_t)(col0 + br) * ldb + k0 + kc);
                Bs[(kc+0)*64 + br] = bv.x; Bs[(kc+1)*64 + br] = bv.y;
                Bs[(kc+2)*64 + br] = bv.z; Bs[(kc+3)*64 + br] = bv.w;
            }
        } else {
            #pragma unroll
            for (int i = 0; i < 2; i++) {
                const int kr = i*8 + (tid >> 4), cn = (tid & 15) << 2;
                *(float4*)(Bs + kr*64 + cn) =
                    *(const float4*)(B + (size_t)(k0 + kr) * ldb + col0 + cn);
            }
        }
        __syncthreads();
        #pragma unroll
        for (int kk = 0; kk < 16; kk++) {
            float4 a = *(const float4*)(As + kk*36 + ty*4);
            float4 b = *(const float4*)(Bs + kk*64 + tx*4);
            acc[0][0] += a.x*b.x; acc[0][1] += a.x*b.y; acc[0][2] += a.x*b.z; acc[0][3] += a.x*b.w;
            acc[1][0] += a.y*b.x; acc[1][1] += a.y*b.y; acc[1][2] += a.y*b.z; acc[1][3] += a.y*b.w;
            acc[2][0] += a.z*b.x; acc[2][1] += a.z*b.y; acc[2][2] += a.z*b.z; acc[2][3] += a.z*b.w;
            acc[3][0] += a.w*b.x; acc[3][1] += a.w*b.y; acc[3][2] += a.w*b.z; acc[3][3] += a.w*b.w;
        }
        __syncthreads();
    }

    float4 bv = make_float4(0.f, 0.f, 0.f, 0.f);
    if (bias) bv = *(const float4*)(bias + col0 + tx*4);
    #pragma unroll
    for (int i = 0; i < 4; i++) {
        float4 o = make_float4(acc[i][0] + bv.x, acc[i][1] + bv.y,
                               acc[i][2] + bv.z, acc[i][3] + bv.w);
        *(float4*)(C + (size_t)(row0 + ty*4 + i) * ldc + col0 + tx*4) = o;
    }
}

// ---------------- launch A ----------------
__global__ void frontA_kernel(const float* __restrict__ memory_key,
                              const float* __restrict__ key_w, const float* __restrict__ key_b,
                              const float* __restrict__ h,
                              const float* __restrict__ query_w, const float* __restrict__ query_b,
                              const float* __restrict__ qq_w, const float* __restrict__ qq_b,
                              const float* __restrict__ kq_w, const float* __restrict__ kq_b,
                              const float* __restrict__ proto_w, const float* __restrict__ proto_b)
{
    __shared__ float As[16*36];
    __shared__ float Bs[16*64];
    const int b = blockIdx.x;
    const int tid = threadIdx.x;

    if (b < 120) {
        gemm_tile<0,1>(As, Bs, memory_key, HID, key_w, HID, key_b,
                       g_key_t, HID, HID, (b >> 2) * 32, (b & 3) * 64);
    } else if (b < 248) {
        const int b2 = b - 120;
        gemm_tile<0,1>(As, Bs, h, HID, query_w, HID, query_b,
                       g_query, HID, HID, (b2 >> 2) * 32, (b2 & 3) * 64);
    } else if (b < 280) {
        const int b2 = b - 248;
        gemm_tile<1,0>(As, Bs, qq_w, HID, kq_w, HID, nullptr,
                       g_Wc, HID, HID, (b2 >> 2) * 32, (b2 & 3) * 64);
    } else if (b < 312) {
        const int b2 = b - 280;
        gemm_tile<0,0>(As, Bs, proto_w, 2*HID, kq_w, HID, nullptr,
                       g_Wout, 2*HID, HID, (b2 >> 2) * 32, (b2 & 3) * 64);
    } else if (b < 328) {
        const int b2 = b - 312;
        #pragma unroll
        for (int t = 0; t < 8; t++) {
            const int idx = t * 128 + tid;
            const int row = b2 * 16 + (idx >> 6);
            const int c4  = idx & 63;
            *(float4*)(g_Wout + (size_t)row * 512 + 256 + c4 * 4) =
                *(const float4*)(proto_w + (size_t)row * 512 + 256 + c4 * 4);
        }
    } else {
        const int j = (b - 328) * 128 + tid;
        float s = 0.f;
        for (int i = 0; i < HID; i++) s += qq_b[i] * kq_w[i * HID + j];
        g_bc[j] = s;
        float s2 = proto_b[j];
        for (int i = 0; i < HID; i++) s2 += kq_b[i] * proto_w[(size_t)j * 512 + i];
        g_bout[j] = s2;
    }
}

// ---------------- launch B ----------------
__global__ void midB_kernel(const float* __restrict__ h)
{
    __shared__ float As[16*36];
    __shared__ float Bs[16*64];
    const int b = blockIdx.x;
    if (b < 128) {
        gemm_tile<0,0>(As, Bs, h, HID, g_Wc, HID, g_bc,
                       g_qk, HID, HID, (b >> 2) * 32, (b & 3) * 64);
    } else {
        const int b2 = b - 128;
        gemm_tile<0,1>(As, Bs, g_query, HID, g_key_t, HID, nullptr,
                       g_W1, NKEY, HID, (b2 / 15) * 32, (b2 % 15) * 64);
    }
}

// ---------------- launch E ----------------
__global__ void outE_kernel(float* __restrict__ out)
{
    __shared__ float As[16*36];
    __shared__ float Bs[16*64];
    const int b = blockIdx.x;
    gemm_tile<0,1>(As, Bs, g_cat, 2*HID, g_Wout, 2*HID, g_bout,
                   out, HID, 2*HID, (b >> 2) * 32, (b & 3) * 64);
}

// ---------------- level 1: top-5 per token ----------------
__global__ void top5_kernel()
{
    const int lane = threadIdx.x & 31;
    const int n = blockIdx.x * 4 + (threadIdx.x >> 5);
    const float* __restrict__ row = g_W1 + (size_t)n * NKEY;

    float v[5]; int ix[5];
    #pragma unroll
    for (int j = 0; j < 5; j++) { v[j] = -INFINITY; ix[j] = 0; }
    for (int k = lane; k < NKEY; k += 32) {
        float x = row[k];
        if (x > v[4]) {
            v[4] = x; ix[4] = k;
            #pragma unroll
            for (int p = 4; p > 0; p--) {
                if (v[p] > v[p-1]) {
                    float tv = v[p]; v[p] = v[p-1]; v[p-1] = tv;
                    int   ti = ix[p]; ix[p] = ix[p-1]; ix[p-1] = ti;
                }
            }
        }
    }

    float selv[5]; int seli[5];
    #pragma unroll
    for (int j = 0; j < 5; j++) {
        float cand = v[0]; int candi = ix[0];
        float bv = cand; int bl = lane;
        #pragma unroll
        for (int off = 16; off; off >>= 1) {
            float ov = __shfl_down_sync(0xffffffffu, bv, off);
            int   ol = __shfl_down_sync(0xffffffffu, bl, off);
            if (ov > bv) { bv = ov; bl = ol; }
        }
        bl = __shfl_sync(0xffffffffu, bl, 0);
        selv[j] = __shfl_sync(0xffffffffu, cand, bl);
        seli[j] = __shfl_sync(0xffffffffu, candi, bl);
        if (lane == bl) {
            #pragma unroll
            for (int p = 0; p < 4; p++) { v[p] = v[p+1]; ix[p] = ix[p+1]; }
            v[4] = -INFINITY;
        }
    }

    const float mx = selv[0];
    float e[5]; float s = 0.f;
    #pragma unroll
    for (int j = 0; j < 5; j++) { e[j] = expf(selv[j] - mx); s += e[j]; }
    const float inv = 1.f / s;

    #pragma unroll
    for (int c = 0; c < 8; c++) {
        const int col = c * 32 + lane;
        float acc = 0.f;
        #pragma unroll
        for (int j = 0; j < 5; j++) acc += e[j] * g_key_t[(size_t)seli[j] * HID + col];
        g_cat[(size_t)n * 512 + 256 + col] = acc * inv;
    }
    #pragma unroll
    for (int j = 0; j < 5; j++)
        if (lane == j) g_cls[n * 5 + j] = seli[j] / DCS;
}

// ---------------- level 2: score 400, radix-select top-100, softmax, gather ----------------
__device__ __forceinline__ unsigned int f2key(float s) {
    unsigned int b = __float_as_uint(s);
    return (b & 0x80000000u) ? ~b : (b | 0x80000000u);   // order-preserving
}

__global__ void queue_kernel(const float* __restrict__ qkey)
{
    __shared__ float qk_s[HID];
    __shared__ float sval[NQ];
    __shared__ unsigned int hist[2048];
    __shared__ int   cls_s[5];
    __shared__ float sred[8];
    __shared__ unsigned int wtot[16];
    __shared__ float smax_s, sinvZ;
    __shared__ unsigned int sh_prefix;
    __shared__ int sh_K, sh_d, sh_cnt;
    __shared__ float sel_w[160];
    __shared__ int   sel_ri[160];
    __shared__ float4 sacc[256];

    const int n = blockIdx.x;
    const int tid = threadIdx.x;
    const int lane = tid & 31, warp = tid >> 5;

    qk_s[tid] = g_qk[(size_t)n * HID + tid];
    if (tid < 5) cls_s[tid] = g_cls[n * 5 + tid];
    if (tid == 0) { sh_prefix = 0; sh_K = TOPKQ; }
    __syncthreads();

    // ---- scoring: warp per candidate, float4 loads ----
    const float4* __restrict__ qs4 = (const float4*)qk_s;
    const float4 a1 = qs4[lane], a2 = qs4[32 + lane];
    for (int it = 0; it < 50; it++) {
        const int m = it * 8 + warp;
        const int k = m / CLSBLK;
        const int r = m - k * CLSBLK;
        const int ri = cls_s[k] * CLSBLK + r;
        const float4* __restrict__ kr4 = (const float4*)(qkey + (size_t)ri * HID);
        const float4 k1 = kr4[lane], k2 = kr4[32 + lane];
        float s = k1.x*a1.x + k1.y*a1.y + k1.z*a1.z + k1.w*a1.w
                + k2.x*a2.x + k2.y*a2.y + k2.z*a2.z + k2.w*a2.w;
        #pragma unroll
        for (int off = 16; off; off >>= 1) s += __shfl_down_sync(0xffffffffu, s, off);
        if (lane == 0) sval[m] = s;
    }
    __syncthreads();

    // each thread owns items: m1 = tid, m2 = tid + 256 (valid if tid < NQ-256)
    const bool has2 = (tid < NQ - 256);
    const float s1 = sval[tid];
    const float s2 = has2 ? sval[tid + 256] : 0.f;
    const unsigned int u1 = f2key(s1);
    const unsigned int u2 = has2 ? f2key(s2) : 0u;

    // ---- block max ----
    float mloc = has2 ? fmaxf(s1, s2) : s1;
    #pragma unroll
    for (int off = 16; off; off >>= 1) mloc = fmaxf(mloc, __shfl_down_sync(0xffffffffu, mloc, off));
    if (lane == 0) sred[warp] = mloc;
    __syncthreads();
    if (tid == 0) {
        float mm = sred[0];
        #pragma unroll
        for (int i = 1; i < 8; i++) mm = fmaxf(mm, sred[i]);
        smax_s = mm;
    }
    __syncthreads();

    // ---- radix select: exact 100th-largest key ----
    #pragma unroll
    for (int pass = 0; pass < 3; pass++) {
        const int shift = (pass == 0) ? 21 : (pass == 1) ? 10 : 0;
        const unsigned int binmask = (pass == 2) ? 1023u : 2047u;
        const unsigned int himask = (pass == 0) ? 0u : (pass == 1) ? 0xFFE00000u : 0xFFFFFC00u;
        const int bpt = (pass == 2) ? 4 : 8;

        #pragma unroll
        for (int i = 0; i < 8; i++) hist[tid * 8 + i] = 0;
        __syncthreads();

        const unsigned int pref = sh_prefix;
        if ((u1 & himask) == (pref & himask)) atomicAdd(&hist[(u1 >> shift) & binmask], 1u);
        if (has2 && (u2 & himask) == (pref & himask)) atomicAdd(&hist[(u2 >> shift) & binmask], 1u);
        __syncthreads();

        unsigned int lsum = 0;
        #pragma unroll
        for (int i = 0; i < 8; i++) if (i < bpt) lsum += hist[tid * bpt + i];
        unsigned int sincl = lsum;                       // inclusive suffix within warp
        #pragma unroll
        for (int off = 1; off < 32; off <<= 1) {
            unsigned int y = __shfl_down_sync(0xffffffffu, sincl, off);
            if (lane + off < 32) sincl += y;
        }
        if (lane == 0) wtot[warp] = sincl;
        __syncthreads();
        unsigned int suf_hi = 0;
        for (int w2 = warp + 1; w2 < 8; w2++) suf_hi += wtot[w2];
        const unsigned int sexcl = suf_hi + (sincl - lsum);   // items in strictly higher bins than my chunk
        const unsigned int K = (unsigned int)sh_K;
        if (lsum > 0 && sexcl < K && sexcl + lsum >= K) {
            unsigned int run = sexcl;
            for (int i = bpt - 1; i >= 0; i--) {
                const unsigned int c = hist[tid * bpt + i];
                if (run < K && run + c >= K) {
                    sh_prefix = pref | ((unsigned int)(tid * bpt + i) << shift);
                    sh_K = (int)(K - run);
                    sh_d = (int)c;
                    break;
                }
                run += c;
            }
        }
        __syncthreads();
    }

    const unsigned int tkey = sh_prefix;
    const float scale_t = (float)sh_K / (float)sh_d;     // need_t / d  (exact for duplicate-row ties)

    // ---- weights + Z ----
    float w1 = 0.f, w2 = 0.f;
    if (u1 > tkey)       w1 = expf(s1 - smax_s);
    else if (u1 == tkey) w1 = expf(s1 - smax_s) * scale_t;
    if (has2) {
        if (u2 > tkey)       w2 = expf(s2 - smax_s);
        else if (u2 == tkey) w2 = expf(s2 - smax_s) * scale_t;
    }
    float z = w1 + w2;
    #pragma unroll
    for (int off = 16; off; off >>= 1) z += __shfl_down_sync(0xffffffffu, z, off);
    if (lane == 0) sred[warp] = z;
    __syncthreads();
    if (tid == 0) {
        float t = 0.f;
        #pragma unroll
        for (int i = 0; i < 8; i++) t += sred[i];
        sinvZ = 1.f / t;
    }
    __syncthreads();
    const float invZ = sinvZ;

    // ---- deterministic compaction (ordered by candidate index) ----
    const bool p1 = (w1 > 0.f);
    unsigned int bal = __ballot_sync(0xffffffffu, p1);
    int lp1 = __popc(bal & ((1u << lane) - 1u));
    if (lane == 0) wtot[warp] = __popc(bal);
    const bool p2 = has2 && (w2 > 0.f);
    unsigned int bal2 = __ballot_sync(0xffffffffu, p2);
    int lp2 = __popc(bal2 & ((1u << lane) - 1u));
    if (lane == 0) wtot[8 + warp] = __popc(bal2);
    __syncthreads();
    int baseA = 0, totA = 0;
    #pragma unroll
    for (int i = 0; i < 8; i++) { if (i < warp) baseA += wtot[i]; totA += wtot[i]; }
    int baseB = totA;
    for (int i = 0; i < warp; i++) baseB += wtot[8 + i];
    if (p1) {
        const int pos = baseA + lp1;
        if (pos < 160) {
            const int m = tid;
            sel_w[pos]  = w1 * invZ;
            sel_ri[pos] = cls_s[m / CLSBLK] * CLSBLK + (m % CLSBLK);
        }
    }
    if (p2) {
        const int pos = baseB + lp2;
        if (pos < 160) {
            const int m = tid + 256;
            sel_w[pos]  = w2 * invZ;
            sel_ri[pos] = cls_s[m / CLSBLK] * CLSBLK + (m % CLSBLK);
        }
    }
    if (tid == 0) {
        int tb = totA;
        #pragma unroll
        for (int i = 0; i < 8; i++) tb += wtot[8 + i];
        sh_cnt = (tb < 160) ? tb : 160;
    }
    __syncthreads();
    const int cnt = sh_cnt;

    // ---- weighted sum of raw rows: 4 row-groups x 64 float4-columns ----
    const int rg = tid >> 6, c4 = tid & 63;
    const float4* __restrict__ q4 = (const float4*)qkey;
    float4 acc = make_float4(0.f, 0.f, 0.f, 0.f);
    for (int j = rg; j < cnt; j += 4) {
        const float w = sel_w[j];
        const float4 v = q4[(size_t)sel_ri[j] * 64 + c4];
        acc.x += w * v.x; acc.y += w * v.y; acc.z += w * v.z; acc.w += w * v.w;
    }
    sacc[rg * 64 + c4] = acc;
    __syncthreads();
    if (rg == 0) {
        const float4 p0v = sacc[c4], p1v = sacc[64 + c4], p2v = sacc[128 + c4], p3v = sacc[192 + c4];
        float4 o = make_float4(p0v.x + p1v.x + p2v.x + p3v.x, p0v.y + p1v.y + p2v.y + p3v.y,
                               p0v.z + p1v.z + p2v.z + p3v.z, p0v.w + p1v.w + p2v.w + p3v.w);
        *(float4*)(g_cat + (size_t)n * 512 + c4 * 4) = o;
    }
}

// ---------------- host ----------------
extern "C" void kernel_launch(void* const* d_in, const int* in_sizes, int n_in,
                              void* d_out, int out_size)
{
    const float* h          = (const float*)d_in[0];
    const float* memory_key = (const float*)d_in[3];
    const float* queue_key  = (const float*)d_in[4];
    const float* key_w      = (const float*)d_in[5];
    const float* key_b      = (const float*)d_in[6];
    const float* query_w    = (const float*)d_in[7];
    const float* query_b    = (const float*)d_in[8];
    const float* kq_w       = (const float*)d_in[9];
    const float* kq_b       = (const float*)d_in[10];
    const float* qq_w       = (const float*)d_in[11];
    const float* qq_b       = (const float*)d_in[12];
    const float* proto_w    = (const float*)d_in[13];
    const float* proto_b    = (const float*)d_in[14];
    float* out = (float*)d_out;

    frontA_kernel<<<330, 128>>>(memory_key, key_w, key_b, h, query_w, query_b,
                                qq_w, qq_b, kq_w, kq_b, proto_w, proto_b);
    midB_kernel<<<608, 128>>>(h);
    top5_kernel<<<NTOK/4, 128>>>();
    queue_kernel<<<NTOK, 256>>>(queue_key);
    outE_kernel<<<128, 128>>>(out);
}